// round 13
// baseline (speedup 1.0000x reference)
#include <cuda_runtime.h>
#include <cuda_fp16.h>
#include <cstdint>

#define MAX_N 100000

// Single-plane fp16 intermediates and weights (transposed [n][k])
__device__ __align__(16) __half g_mid1[MAX_N * 64];
__device__ __align__(16) __half g_mid2[MAX_N * 64];
__device__ __align__(16) __half g_w1[64 * 256];
__device__ __align__(16) __half g_w2[9 * 64 * 64];
__device__ __align__(16) __half g_w3[256 * 64];

// ---------------- helpers ----------------
__device__ __forceinline__ uint32_t smem_u32(const void* p) {
    uint32_t a;
    asm("{ .reg .u64 t; cvta.to.shared.u64 t, %1; cvt.u32.u64 %0, t; }" : "=r"(a) : "l"(p));
    return a;
}
__device__ __forceinline__ uint32_t pack2h(float a, float b) {
    __half2 h = __floats2half2_rn(a, b);
    return *(uint32_t*)&h;
}
__device__ __forceinline__ void cpa16(uint32_t dst, const void* src, int srcsize) {
    asm volatile("cp.async.cg.shared.global [%0], [%1], 16, %2;"
                 :: "r"(dst), "l"(src), "r"(srcsize));
}
#define CP_COMMIT() asm volatile("cp.async.commit_group;" ::: "memory")
#define CP_WAIT1()  asm volatile("cp.async.wait_group 1;" ::: "memory")
#define CP_WAIT0()  asm volatile("cp.async.wait_group 0;" ::: "memory")

__device__ __forceinline__ void stcs2(float* p, float x, float y) {
    asm volatile("st.global.cs.v2.f32 [%0], {%1, %2};" :: "l"(p), "f"(x), "f"(y) : "memory");
}

__device__ __forceinline__ void mma_f16(float* c, const uint32_t* a, uint32_t b0, uint32_t b1) {
    asm volatile(
        "mma.sync.aligned.m16n8k16.row.col.f32.f16.f16.f32 "
        "{%0,%1,%2,%3}, {%4,%5,%6,%7}, {%8,%9}, {%0,%1,%2,%3};"
        : "+f"(c[0]), "+f"(c[1]), "+f"(c[2]), "+f"(c[3])
        : "r"(a[0]), "r"(a[1]), "r"(a[2]), "r"(a[3]), "r"(b0), "r"(b1));
}
__device__ __forceinline__ void ldsm4(uint32_t* r, uint32_t a) {
    asm volatile("ldmatrix.sync.aligned.m8n8.x4.shared.b16 {%0,%1,%2,%3}, [%4];"
                 : "=r"(r[0]), "=r"(r[1]), "=r"(r[2]), "=r"(r[3]) : "r"(a));
}

struct AF { uint32_t h[4]; };
struct BF { uint32_t h[4]; };

// A plane: [rows][64 fp16] stride 128B, chunk swizzle c^=row&7. kc0 in {0,2,4,6}.
__device__ __forceinline__ AF load_af(uint32_t aU, int lane, int m0, int kc0) {
    int row = m0 + (lane & 15);
    int kc = kc0 + (lane >> 4);
    uint32_t off = row * 128 + (((kc ^ row) & 7)) * 16;
    AF f; ldsm4(f.h, aU + off);
    return f;
}
// B plane: [n rows][K fp16] stride bytes; frags for n0 and n0+8 at {kc0,kc0+1}
__device__ __forceinline__ BF load_bf(uint32_t bU, int stride, int lane, int n0, int kc0) {
    int row = n0 + (lane & 7) + ((lane >> 4) << 3);
    int kc = kc0 + ((lane >> 3) & 1);
    uint32_t off = row * stride + ((kc & ~7) | ((kc ^ row) & 7)) * 16;
    BF f; ldsm4(f.h, bU + off);
    return f;
}

// ---------------- prep: round weights to fp16, transpose to [n][k] --------
__global__ void prep_weights(const float* __restrict__ w1, const float* __restrict__ w2,
                             const float* __restrict__ w3) {
    int tid = blockIdx.x * blockDim.x + threadIdx.x;
    int nt = gridDim.x * blockDim.x;
    for (int i = tid; i < 64 * 256; i += nt) {
        int n = i >> 8, k = i & 255;
        g_w1[i] = __float2half_rn(w1[k * 64 + n]);
    }
    for (int i = tid; i < 9 * 64 * 64; i += nt) {
        int ko = i >> 12, n = (i >> 6) & 63, k = i & 63;
        g_w2[i] = __float2half_rn(w2[ko * 4096 + k * 64 + n]);
    }
    for (int i = tid; i < 256 * 64; i += nt) {
        int n = i >> 6, k = i & 63;
        g_w3[i] = __float2half_rn(w3[k * 256 + n]);
    }
}

// ===========================================================================
// conv1: M64 tiles, K=256 (4 panels of 64), 256 thr, 3 CTAs/SM.
// smem: B 32KB @0 | A 2buf x 8KB @32768 = 48KB
// ===========================================================================
__global__ void __launch_bounds__(256, 3) conv1_k(
    const float* __restrict__ feat, const float* __restrict__ scale,
    const float* __restrict__ bias, int N, int tiles)
{
    extern __shared__ char smem[];
    const uint32_t smU = smem_u32(smem);
    const int tid = threadIdx.x, w = tid >> 5, lane = tid & 31;
    const int g = lane >> 2, tg = lane & 3;
    const int m0w = (w & 1) * 32, n0w = (w >> 1) * 16;
    const int sr = tid >> 2, sq = tid & 3;

    for (int e = tid; e < 2048; e += 256) {
        int n = e >> 5, kc = e & 31;
        int off = n * 512 + ((kc & ~7) | ((kc ^ n) & 7)) * 16;
        *(uint4*)(smem + off) = *(const uint4*)(g_w1 + n * 256 + kc * 8);
    }

    float4 nx[4];
    {
        int grow = (blockIdx.x << 6) + sr;
        if (grow < N) {
            const float4* s = (const float4*)(feat + (size_t)grow * 256 + sq * 16);
            nx[0] = s[0]; nx[1] = s[1]; nx[2] = s[2]; nx[3] = s[3];
        } else nx[0] = nx[1] = nx[2] = nx[3] = make_float4(0.f, 0.f, 0.f, 0.f);
    }
    __syncthreads();

    for (int t = blockIdx.x; t < tiles; t += gridDim.x) {
        const int row0 = t << 6;
        float C[2][2][4] = {};
        #pragma unroll
        for (int p = 0; p < 4; p++) {
            char* A = smem + 32768 + (p & 1) * 8192;
            #pragma unroll
            for (int j = 0; j < 2; j++) {
                float4 u = nx[2 * j], v = nx[2 * j + 1];
                uint4 H;
                H.x = pack2h(u.x, u.y); H.y = pack2h(u.z, u.w);
                H.z = pack2h(v.x, v.y); H.w = pack2h(v.z, v.w);
                int c = sq * 2 + j;
                int off = sr * 128 + ((c ^ sr) & 7) * 16;
                *(uint4*)(A + off) = H;
            }
            __syncthreads();
            {
                int tn = (p < 3) ? t : t + gridDim.x;
                int pn = (p < 3) ? p + 1 : 0;
                int grow = (tn << 6) + sr;
                if (grow < N) {
                    const float4* s = (const float4*)(feat + (size_t)grow * 256 + pn * 64 + sq * 16);
                    nx[0] = s[0]; nx[1] = s[1]; nx[2] = s[2]; nx[3] = s[3];
                } else nx[0] = nx[1] = nx[2] = nx[3] = make_float4(0.f, 0.f, 0.f, 0.f);
            }
            const uint32_t AU = smU + 32768 + (p & 1) * 8192;
            #pragma unroll
            for (int s = 0; s < 4; s++) {
                AF a0 = load_af(AU, lane, m0w, s * 2);
                AF a1 = load_af(AU, lane, m0w + 16, s * 2);
                BF b = load_bf(smU, 512, lane, n0w, p * 8 + s * 2);
                mma_f16(C[0][0], a0.h, b.h[0], b.h[1]);
                mma_f16(C[0][1], a0.h, b.h[2], b.h[3]);
                mma_f16(C[1][0], a1.h, b.h[0], b.h[1]);
                mma_f16(C[1][1], a1.h, b.h[2], b.h[3]);
            }
        }
        #pragma unroll
        for (int mf = 0; mf < 2; mf++)
        #pragma unroll
        for (int nf = 0; nf < 2; nf++) {
            int row = row0 + m0w + mf * 16 + g;
            int col = n0w + nf * 8 + 2 * tg;
            float s0 = __ldg(scale + col), s1 = __ldg(scale + col + 1);
            float bb0 = __ldg(bias + col), bb1 = __ldg(bias + col + 1);
            if (row < N) {
                *(uint32_t*)(g_mid1 + (size_t)row * 64 + col) =
                    pack2h(fmaxf(fmaf(C[mf][nf][0], s0, bb0), 0.f),
                           fmaxf(fmaf(C[mf][nf][1], s1, bb1), 0.f));
            }
            if (row + 8 < N) {
                *(uint32_t*)(g_mid1 + (size_t)(row + 8) * 64 + col) =
                    pack2h(fmaxf(fmaf(C[mf][nf][2], s0, bb0), 0.f),
                           fmaxf(fmaf(C[mf][nf][3], s1, bb1), 0.f));
            }
        }
    }
}

// ===========================================================================
// conv2: M64 tiles, 9 ko in 5 pair-phases ({0,1}..{8}); 256 thr, 2 CTAs/SM.
// Two 16KB double-wide A buffers; 6 barriers/tile (was 10); 4 cp.async/issue.
// smem: B 72KB @0 | A 2 x 16KB @73728 = 104KB
// ===========================================================================
__global__ void __launch_bounds__(256, 2) conv2_k(
    const int* __restrict__ nbr, const float* __restrict__ scale,
    const float* __restrict__ bias, int N, int tiles)
{
    extern __shared__ char smem[];
    const uint32_t smU = smem_u32(smem);
    const uint32_t AU = smU + 73728;
    const int tid = threadIdx.x, w = tid >> 5, lane = tid & 31;
    const int g = lane >> 2, tg = lane & 3;
    const int m0w = (w & 1) * 32, n0w = (w >> 1) * 16;
    const int sr = tid >> 2, sq = tid & 3;

    for (int e = tid; e < 4608; e += 256) {
        int ko = e >> 9, r = e & 511, n = r >> 3, kc = r & 7;
        int off = n * 128 + ((kc ^ n) & 7) * 16;
        *(uint4*)(smem + ko * 8192 + off) = *(const uint4*)(g_w2 + ko * 4096 + n * 64 + kc * 8);
    }
    __syncthreads();

    const int c0 = sq * 2, c1 = sq * 2 + 1;
    const uint32_t offA0 = sr * 128 + ((c0 ^ sr) & 7) * 16;
    const uint32_t offA1 = sr * 128 + ((c1 ^ sr) & 7) * 16;

    for (int t = blockIdx.x; t < tiles; t += gridDim.x) {
        const int row0 = t << 6;
        const int grow = row0 + sr;
        int nidx9[9];
        #pragma unroll
        for (int ko = 0; ko < 9; ko++)
            nidx9[ko] = (grow < N) ? __ldg(nbr + (size_t)grow * 9 + ko) : N;

        {   // prologue: phase 0 (ko 0 -> dbuf0.slot0, ko 1 -> dbuf0.slot1)
            #pragma unroll
            for (int s = 0; s < 2; s++) {
                int nn = nidx9[s];
                int sz = (nn < N) ? 16 : 0;
                const __half* src = g_mid1 + (size_t)(nn < N ? nn : 0) * 64;
                uint32_t Ab = AU + s * 8192;
                cpa16(Ab + offA0, src + c0 * 8, sz);
                cpa16(Ab + offA1, src + c1 * 8, sz);
            }
            CP_COMMIT();
        }

        float C[2][2][4] = {};
        #pragma unroll
        for (int p = 0; p < 5; p++) {
            CP_WAIT0();              // phase p gathers landed (only group in flight)
            __syncthreads();         // visible to all; all warps done with MMA p-1
            if (p < 4) {             // issue phase p+1 into the other double-buffer
                uint32_t Db = AU + ((p + 1) & 1) * 16384;
                #pragma unroll
                for (int s = 0; s < 2; s++) {
                    int ko2 = 2 * (p + 1) + s;
                    int nn = (ko2 < 9) ? nidx9[ko2] : N;
                    int sz = (nn < N) ? 16 : 0;
                    const __half* src = g_mid1 + (size_t)(nn < N ? nn : 0) * 64;
                    uint32_t Ab = Db + s * 8192;
                    cpa16(Ab + offA0, src + c0 * 8, sz);
                    cpa16(Ab + offA1, src + c1 * 8, sz);
                }
                CP_COMMIT();
            }
            const uint32_t Db = AU + (p & 1) * 16384;
            const int nslots = (p < 4) ? 2 : 1;
            #pragma unroll
            for (int sl = 0; sl < 2; sl++) {
                if (sl >= nslots) break;
                int ko = 2 * p + sl;
                const uint32_t AbU = Db + sl * 8192;
                const uint32_t BU = smU + ko * 8192;
                #pragma unroll
                for (int s = 0; s < 4; s++) {
                    AF a0 = load_af(AbU, lane, m0w, s * 2);
                    AF a1 = load_af(AbU, lane, m0w + 16, s * 2);
                    BF b = load_bf(BU, 128, lane, n0w, s * 2);
                    mma_f16(C[0][0], a0.h, b.h[0], b.h[1]);
                    mma_f16(C[0][1], a0.h, b.h[2], b.h[3]);
                    mma_f16(C[1][0], a1.h, b.h[0], b.h[1]);
                    mma_f16(C[1][1], a1.h, b.h[2], b.h[3]);
                }
            }
        }
        #pragma unroll
        for (int mf = 0; mf < 2; mf++)
        #pragma unroll
        for (int nf = 0; nf < 2; nf++) {
            int row = row0 + m0w + mf * 16 + g;
            int col = n0w + nf * 8 + 2 * tg;
            float s0 = __ldg(scale + col), s1 = __ldg(scale + col + 1);
            float bb0 = __ldg(bias + col), bb1 = __ldg(bias + col + 1);
            if (row < N) {
                *(uint32_t*)(g_mid2 + (size_t)row * 64 + col) =
                    pack2h(fmaxf(fmaf(C[mf][nf][0], s0, bb0), 0.f),
                           fmaxf(fmaf(C[mf][nf][1], s1, bb1), 0.f));
            }
            if (row + 8 < N) {
                *(uint32_t*)(g_mid2 + (size_t)(row + 8) * 64 + col) =
                    pack2h(fmaxf(fmaf(C[mf][nf][2], s0, bb0), 0.f),
                           fmaxf(fmaf(C[mf][nf][3], s1, bb1), 0.f));
            }
        }
        __syncthreads();   // protect dbuf0 before next tile's prologue
    }
}

// ===========================================================================
// conv3 (R12 config): M128 K64, two N128 halves; 256 thr, 2 CTAs/SM.
// smem: B 16KB @0 | A 2buf x 16KB @16384 = 48KB.  out stored with st.cs.
// ===========================================================================
__global__ void __launch_bounds__(256, 2) conv3_k(
    const float* __restrict__ feat, const float* __restrict__ scale,
    const float* __restrict__ bias, float* __restrict__ out, int N, int tiles)
{
    extern __shared__ char smem[];
    const uint32_t smU = smem_u32(smem);
    const uint32_t AU = smU + 16384;
    const int tid = threadIdx.x, w = tid >> 5, lane = tid & 31;
    const int g = lane >> 2, tg = lane & 3;
    const int nhalf = blockIdx.x & 1;
    const int t0 = blockIdx.x >> 1, tstep = gridDim.x >> 1;
    const int m0w = (w & 3) * 32, n0l = (w >> 2) * 64;
    const int colbase = nhalf * 128;
    const int sr = tid >> 1, sq = tid & 1;

    for (int e = tid; e < 1024; e += 256) {
        int n = e >> 3, kc = e & 7;
        int off = n * 128 + ((kc ^ n) & 7) * 16;
        *(uint4*)(smem + off) = *(const uint4*)(g_w3 + (colbase + n) * 64 + kc * 8);
    }

    {   // prologue: prefetch tile t0 -> buf0
        int grow = (t0 << 7) + sr;
        int sz = (grow < N) ? 16 : 0;
        const __half* src = g_mid2 + (size_t)(grow < N ? grow : 0) * 64;
        #pragma unroll
        for (int j = 0; j < 4; j++) {
            int c = sq * 4 + j;
            uint32_t off = sr * 128 + ((c ^ sr) & 7) * 16;
            cpa16(AU + off, src + c * 8, sz);
        }
        CP_COMMIT();
    }

    int cnt = 0;
    for (int t = t0; t < tiles; t += tstep) {
        const int row0 = t << 7;
        const int b = cnt & 1;
        {   // prefetch next tile into other buffer
            int grow = ((t + tstep) << 7) + sr;
            int sz = (grow < N) ? 16 : 0;
            const __half* src = g_mid2 + (size_t)(grow < N ? grow : 0) * 64;
            uint32_t Ab = AU + (b ^ 1) * 16384;
            #pragma unroll
            for (int j = 0; j < 4; j++) {
                int c = sq * 4 + j;
                uint32_t off = sr * 128 + ((c ^ sr) & 7) * 16;
                cpa16(Ab + off, src + c * 8, sz);
            }
            CP_COMMIT();
        }
        CP_WAIT1();
        __syncthreads();

        const uint32_t AbU = AU + b * 16384;
        float C[2][8][4] = {};
        #pragma unroll
        for (int s = 0; s < 4; s++) {
            AF a0 = load_af(AbU, lane, m0w, s * 2);
            AF a1 = load_af(AbU, lane, m0w + 16, s * 2);
            #pragma unroll
            for (int nb = 0; nb < 4; nb++) {
                BF bb = load_bf(smU, 128, lane, n0l + nb * 16, s * 2);
                mma_f16(C[0][2 * nb],     a0.h, bb.h[0], bb.h[1]);
                mma_f16(C[0][2 * nb + 1], a0.h, bb.h[2], bb.h[3]);
                mma_f16(C[1][2 * nb],     a1.h, bb.h[0], bb.h[1]);
                mma_f16(C[1][2 * nb + 1], a1.h, bb.h[2], bb.h[3]);
            }
        }
        #pragma unroll
        for (int mf = 0; mf < 2; mf++)
        #pragma unroll
        for (int nf = 0; nf < 8; nf++) {
            int row = row0 + m0w + mf * 16 + g;
            int col = colbase + n0l + nf * 8 + 2 * tg;
            float s0 = __ldg(scale + col), s1 = __ldg(scale + col + 1);
            float bb0 = __ldg(bias + col), bb1 = __ldg(bias + col + 1);
            if (row < N) {
                float2 f = *(const float2*)(feat + (size_t)row * 256 + col);
                stcs2(out + (size_t)row * 256 + col,
                      fmaxf(fmaf(C[mf][nf][0], s0, bb0) + f.x, 0.f),
                      fmaxf(fmaf(C[mf][nf][1], s1, bb1) + f.y, 0.f));
            }
            if (row + 8 < N) {
                float2 f = *(const float2*)(feat + (size_t)(row + 8) * 256 + col);
                stcs2(out + (size_t)(row + 8) * 256 + col,
                      fmaxf(fmaf(C[mf][nf][2], s0, bb0) + f.x, 0.f),
                      fmaxf(fmaf(C[mf][nf][3], s1, bb1) + f.y, 0.f));
            }
        }
        __syncthreads();
        cnt++;
    }
}

// ---------------------------------------------------------------------------
extern "C" void kernel_launch(void* const* d_in, const int* in_sizes, int n_in,
                              void* d_out, int out_size)
{
    const float* feat = (const float*)d_in[0];
    const int*   nbr  = (const int*)  d_in[1];
    const float* w1   = (const float*)d_in[2];
    const float* s1   = (const float*)d_in[3];
    const float* b1   = (const float*)d_in[4];
    const float* w2   = (const float*)d_in[5];
    const float* s2   = (const float*)d_in[6];
    const float* b2   = (const float*)d_in[7];
    const float* w3   = (const float*)d_in[8];
    const float* s3   = (const float*)d_in[9];
    const float* b3   = (const float*)d_in[10];
    float* out = (float*)d_out;

    int N = in_sizes[0] / 256;
    if (N > MAX_N) N = MAX_N;
    int tiles64  = (N + 63) >> 6;
    int tiles128 = (N + 127) >> 7;

    const int sm1 = 49152;    // 48KB  -> 3 CTAs/SM
    const int sm2 = 106496;   // 104KB -> 2 CTAs/SM
    const int sm3 = 49152;    // 48KB  -> 2 CTAs/SM

    cudaFuncSetAttribute(conv1_k, cudaFuncAttributeMaxDynamicSharedMemorySize, sm1);
    cudaFuncSetAttribute(conv2_k, cudaFuncAttributeMaxDynamicSharedMemorySize, sm2);
    cudaFuncSetAttribute(conv3_k, cudaFuncAttributeMaxDynamicSharedMemorySize, sm3);

    prep_weights<<<64, 256>>>(w1, w2, w3);
    conv1_k<<<444, 256, sm1>>>(feat, s1, b1, N, tiles64);
    conv2_k<<<296, 256, sm2>>>(nbr, s2, b2, N, tiles64);
    conv3_k<<<296, 256, sm3>>>(feat, s3, b3, out, N, tiles128);
}

// round 15
// speedup vs baseline: 1.0057x; 1.0057x over previous
#include <cuda_runtime.h>
#include <cuda_fp16.h>
#include <cstdint>

#define MAX_N 100000

// Single-plane fp16 intermediates and weights (transposed [n][k])
__device__ __align__(16) __half g_mid1[MAX_N * 64];
__device__ __align__(16) __half g_mid2[MAX_N * 64];
__device__ __align__(16) __half g_w1[64 * 256];
__device__ __align__(16) __half g_w2[9 * 64 * 64];
__device__ __align__(16) __half g_w3[256 * 64];

// ---------------- helpers ----------------
__device__ __forceinline__ uint32_t smem_u32(const void* p) {
    uint32_t a;
    asm("{ .reg .u64 t; cvta.to.shared.u64 t, %1; cvt.u32.u64 %0, t; }" : "=r"(a) : "l"(p));
    return a;
}
__device__ __forceinline__ uint32_t pack2h(float a, float b) {
    __half2 h = __floats2half2_rn(a, b);
    return *(uint32_t*)&h;
}
__device__ __forceinline__ void cpa16(uint32_t dst, const void* src, int srcsize) {
    asm volatile("cp.async.cg.shared.global [%0], [%1], 16, %2;"
                 :: "r"(dst), "l"(src), "r"(srcsize));
}
#define CP_COMMIT() asm volatile("cp.async.commit_group;" ::: "memory")
#define CP_WAIT1()  asm volatile("cp.async.wait_group 1;" ::: "memory")
#define CP_WAITN(k) asm volatile("cp.async.wait_group " #k ";" ::: "memory")

__device__ __forceinline__ void stcs2(float* p, float x, float y) {
    asm volatile("st.global.cs.v2.f32 [%0], {%1, %2};" :: "l"(p), "f"(x), "f"(y) : "memory");
}

__device__ __forceinline__ void mma_f16(float* c, const uint32_t* a, uint32_t b0, uint32_t b1) {
    asm volatile(
        "mma.sync.aligned.m16n8k16.row.col.f32.f16.f16.f32 "
        "{%0,%1,%2,%3}, {%4,%5,%6,%7}, {%8,%9}, {%0,%1,%2,%3};"
        : "+f"(c[0]), "+f"(c[1]), "+f"(c[2]), "+f"(c[3])
        : "r"(a[0]), "r"(a[1]), "r"(a[2]), "r"(a[3]), "r"(b0), "r"(b1));
}
__device__ __forceinline__ void ldsm4(uint32_t* r, uint32_t a) {
    asm volatile("ldmatrix.sync.aligned.m8n8.x4.shared.b16 {%0,%1,%2,%3}, [%4];"
                 : "=r"(r[0]), "=r"(r[1]), "=r"(r[2]), "=r"(r[3]) : "r"(a));
}

struct AF { uint32_t h[4]; };
struct BF { uint32_t h[4]; };

// A plane: [rows][64 fp16] stride 128B, chunk swizzle c^=row&7. kc0 in {0,2,4,6}.
__device__ __forceinline__ AF load_af(uint32_t aU, int lane, int m0, int kc0) {
    int row = m0 + (lane & 15);
    int kc = kc0 + (lane >> 4);
    uint32_t off = row * 128 + (((kc ^ row) & 7)) * 16;
    AF f; ldsm4(f.h, aU + off);
    return f;
}
// B plane: [n rows][K fp16] stride bytes; frags for n0 and n0+8 at {kc0,kc0+1}
__device__ __forceinline__ BF load_bf(uint32_t bU, int stride, int lane, int n0, int kc0) {
    int row = n0 + (lane & 7) + ((lane >> 4) << 3);
    int kc = kc0 + ((lane >> 3) & 1);
    uint32_t off = row * stride + ((kc & ~7) | ((kc ^ row) & 7)) * 16;
    BF f; ldsm4(f.h, bU + off);
    return f;
}

// ---------------- prep: round weights to fp16, transpose to [n][k] --------
__global__ void prep_weights(const float* __restrict__ w1, const float* __restrict__ w2,
                             const float* __restrict__ w3) {
    int tid = blockIdx.x * blockDim.x + threadIdx.x;
    int nt = gridDim.x * blockDim.x;
    for (int i = tid; i < 64 * 256; i += nt) {
        int n = i >> 8, k = i & 255;
        g_w1[i] = __float2half_rn(w1[k * 64 + n]);
    }
    for (int i = tid; i < 9 * 64 * 64; i += nt) {
        int ko = i >> 12, n = (i >> 6) & 63, k = i & 63;
        g_w2[i] = __float2half_rn(w2[ko * 4096 + k * 64 + n]);
    }
    for (int i = tid; i < 256 * 64; i += nt) {
        int n = i >> 6, k = i & 63;
        g_w3[i] = __float2half_rn(w3[k * 256 + n]);
    }
}

// ===========================================================================
// conv1: M64 tiles, K=256 (4 panels of 64), 256 thr, 3 CTAs/SM.
// smem: B 32KB @0 | A 2buf x 8KB @32768 = 48KB
// ===========================================================================
__global__ void __launch_bounds__(256, 3) conv1_k(
    const float* __restrict__ feat, const float* __restrict__ scale,
    const float* __restrict__ bias, int N, int tiles)
{
    extern __shared__ char smem[];
    const uint32_t smU = smem_u32(smem);
    const int tid = threadIdx.x, w = tid >> 5, lane = tid & 31;
    const int g = lane >> 2, tg = lane & 3;
    const int m0w = (w & 1) * 32, n0w = (w >> 1) * 16;
    const int sr = tid >> 2, sq = tid & 3;

    for (int e = tid; e < 2048; e += 256) {
        int n = e >> 5, kc = e & 31;
        int off = n * 512 + ((kc & ~7) | ((kc ^ n) & 7)) * 16;
        *(uint4*)(smem + off) = *(const uint4*)(g_w1 + n * 256 + kc * 8);
    }

    float4 nx[4];
    {
        int grow = (blockIdx.x << 6) + sr;
        if (grow < N) {
            const float4* s = (const float4*)(feat + (size_t)grow * 256 + sq * 16);
            nx[0] = s[0]; nx[1] = s[1]; nx[2] = s[2]; nx[3] = s[3];
        } else nx[0] = nx[1] = nx[2] = nx[3] = make_float4(0.f, 0.f, 0.f, 0.f);
    }
    __syncthreads();

    for (int t = blockIdx.x; t < tiles; t += gridDim.x) {
        const int row0 = t << 6;
        float C[2][2][4] = {};
        #pragma unroll
        for (int p = 0; p < 4; p++) {
            char* A = smem + 32768 + (p & 1) * 8192;
            #pragma unroll
            for (int j = 0; j < 2; j++) {
                float4 u = nx[2 * j], v = nx[2 * j + 1];
                uint4 H;
                H.x = pack2h(u.x, u.y); H.y = pack2h(u.z, u.w);
                H.z = pack2h(v.x, v.y); H.w = pack2h(v.z, v.w);
                int c = sq * 2 + j;
                int off = sr * 128 + ((c ^ sr) & 7) * 16;
                *(uint4*)(A + off) = H;
            }
            __syncthreads();
            {
                int tn = (p < 3) ? t : t + gridDim.x;
                int pn = (p < 3) ? p + 1 : 0;
                int grow = (tn << 6) + sr;
                if (grow < N) {
                    const float4* s = (const float4*)(feat + (size_t)grow * 256 + pn * 64 + sq * 16);
                    nx[0] = s[0]; nx[1] = s[1]; nx[2] = s[2]; nx[3] = s[3];
                } else nx[0] = nx[1] = nx[2] = nx[3] = make_float4(0.f, 0.f, 0.f, 0.f);
            }
            const uint32_t AU = smU + 32768 + (p & 1) * 8192;
            #pragma unroll
            for (int s = 0; s < 4; s++) {
                AF a0 = load_af(AU, lane, m0w, s * 2);
                AF a1 = load_af(AU, lane, m0w + 16, s * 2);
                BF b = load_bf(smU, 512, lane, n0w, p * 8 + s * 2);
                mma_f16(C[0][0], a0.h, b.h[0], b.h[1]);
                mma_f16(C[0][1], a0.h, b.h[2], b.h[3]);
                mma_f16(C[1][0], a1.h, b.h[0], b.h[1]);
                mma_f16(C[1][1], a1.h, b.h[2], b.h[3]);
            }
        }
        #pragma unroll
        for (int mf = 0; mf < 2; mf++)
        #pragma unroll
        for (int nf = 0; nf < 2; nf++) {
            int row = row0 + m0w + mf * 16 + g;
            int col = n0w + nf * 8 + 2 * tg;
            float s0 = __ldg(scale + col), s1 = __ldg(scale + col + 1);
            float bb0 = __ldg(bias + col), bb1 = __ldg(bias + col + 1);
            if (row < N) {
                *(uint32_t*)(g_mid1 + (size_t)row * 64 + col) =
                    pack2h(fmaxf(fmaf(C[mf][nf][0], s0, bb0), 0.f),
                           fmaxf(fmaf(C[mf][nf][1], s1, bb1), 0.f));
            }
            if (row + 8 < N) {
                *(uint32_t*)(g_mid1 + (size_t)(row + 8) * 64 + col) =
                    pack2h(fmaxf(fmaf(C[mf][nf][2], s0, bb0), 0.f),
                           fmaxf(fmaf(C[mf][nf][3], s1, bb1), 0.f));
            }
        }
    }
}

// ===========================================================================
// conv2: M64 tiles, 9x gathered [64,64]@[64,64], 256 thr, 2 CTAs/SM.
// DEPTH-5 gather pipeline: 5 A buffers, 4 ko-groups in flight.
// smem: B 72KB @0 | A 5 x 8KB @73728 -> 112KB
// ===========================================================================
__global__ void __launch_bounds__(256, 2) conv2_k(
    const int* __restrict__ nbr, const float* __restrict__ scale,
    const float* __restrict__ bias, int N, int tiles)
{
    extern __shared__ char smem[];
    const uint32_t smU = smem_u32(smem);
    const uint32_t AU = smU + 73728;
    const int tid = threadIdx.x, w = tid >> 5, lane = tid & 31;
    const int g = lane >> 2, tg = lane & 3;
    const int m0w = (w & 1) * 32, n0w = (w >> 1) * 16;
    const int sr = tid >> 2, sq = tid & 3;

    for (int e = tid; e < 4608; e += 256) {
        int ko = e >> 9, r = e & 511, n = r >> 3, kc = r & 7;
        int off = n * 128 + ((kc ^ n) & 7) * 16;
        *(uint4*)(smem + ko * 8192 + off) = *(const uint4*)(g_w2 + ko * 4096 + n * 64 + kc * 8);
    }
    __syncthreads();

    const int c0 = sq * 2, c1 = sq * 2 + 1;
    const uint32_t offA0 = sr * 128 + ((c0 ^ sr) & 7) * 16;
    const uint32_t offA1 = sr * 128 + ((c1 ^ sr) & 7) * 16;

    for (int t = blockIdx.x; t < tiles; t += gridDim.x) {
        const int row0 = t << 6;
        const int grow = row0 + sr;
        int nidx9[9];
        #pragma unroll
        for (int ko = 0; ko < 9; ko++)
            nidx9[ko] = (grow < N) ? __ldg(nbr + (size_t)grow * 9 + ko) : N;

        // prologue: issue ko = 0..3 into buf 0..3 (4 groups in flight)
        #pragma unroll
        for (int k0 = 0; k0 < 4; k0++) {
            int nn = nidx9[k0];
            int sz = (nn < N) ? 16 : 0;
            const __half* src = g_mid1 + (size_t)(nn < N ? nn : 0) * 64;
            uint32_t Ab = AU + k0 * 8192;
            cpa16(Ab + offA0, src + c0 * 8, sz);
            cpa16(Ab + offA1, src + c1 * 8, sz);
            CP_COMMIT();
        }

        float C[2][2][4] = {};
        #pragma unroll
        for (int ko = 0; ko < 9; ko++) {
            // wait so that group `ko` has completed (exact outstanding counts)
            if (ko <= 5)      { CP_WAITN(3); }
            else if (ko == 6) { CP_WAITN(2); }
            else if (ko == 7) { CP_WAITN(1); }
            else              { CP_WAITN(0); }
            __syncthreads();
            if (ko < 5) {   // issue ko+4 into buf (ko+4)%5 (= (ko-1)%5, already consumed)
                int ko4 = ko + 4;
                int nn = nidx9[ko4];
                int sz = (nn < N) ? 16 : 0;
                const __half* src = g_mid1 + (size_t)(nn < N ? nn : 0) * 64;
                int b4 = ko4 - (ko4 >= 5 ? 5 : 0);
                uint32_t Ab = AU + b4 * 8192;
                cpa16(Ab + offA0, src + c0 * 8, sz);
                cpa16(Ab + offA1, src + c1 * 8, sz);
                CP_COMMIT();
            }
            int bko = ko; if (bko >= 5) bko -= 5;
            const uint32_t AbU = AU + bko * 8192;
            const uint32_t BU = smU + ko * 8192;
            #pragma unroll
            for (int s = 0; s < 4; s++) {
                AF a0 = load_af(AbU, lane, m0w, s * 2);
                AF a1 = load_af(AbU, lane, m0w + 16, s * 2);
                BF b = load_bf(BU, 128, lane, n0w, s * 2);
                mma_f16(C[0][0], a0.h, b.h[0], b.h[1]);
                mma_f16(C[0][1], a0.h, b.h[2], b.h[3]);
                mma_f16(C[1][0], a1.h, b.h[0], b.h[1]);
                mma_f16(C[1][1], a1.h, b.h[2], b.h[3]);
            }
        }
        #pragma unroll
        for (int mf = 0; mf < 2; mf++)
        #pragma unroll
        for (int nf = 0; nf < 2; nf++) {
            int row = row0 + m0w + mf * 16 + g;
            int col = n0w + nf * 8 + 2 * tg;
            float s0 = __ldg(scale + col), s1 = __ldg(scale + col + 1);
            float bb0 = __ldg(bias + col), bb1 = __ldg(bias + col + 1);
            if (row < N) {
                *(uint32_t*)(g_mid2 + (size_t)row * 64 + col) =
                    pack2h(fmaxf(fmaf(C[mf][nf][0], s0, bb0), 0.f),
                           fmaxf(fmaf(C[mf][nf][1], s1, bb1), 0.f));
            }
            if (row + 8 < N) {
                *(uint32_t*)(g_mid2 + (size_t)(row + 8) * 64 + col) =
                    pack2h(fmaxf(fmaf(C[mf][nf][2], s0, bb0), 0.f),
                           fmaxf(fmaf(C[mf][nf][3], s1, bb1), 0.f));
            }
        }
        __syncthreads();   // protect buf 0..3 before next tile's prologue
    }
}

// ===========================================================================
// conv3: M128 K64, two N128 halves; 256 thr, 2 CTAs/SM.
// out: st.cs (evict-first) to preserve feat L2 residency.
// smem: B 16KB @0 | A 2buf x 16KB @16384 = 48KB
// ===========================================================================
__global__ void __launch_bounds__(256, 2) conv3_k(
    const float* __restrict__ feat, const float* __restrict__ scale,
    const float* __restrict__ bias, float* __restrict__ out, int N, int tiles)
{
    extern __shared__ char smem[];
    const uint32_t smU = smem_u32(smem);
    const uint32_t AU = smU + 16384;
    const int tid = threadIdx.x, w = tid >> 5, lane = tid & 31;
    const int g = lane >> 2, tg = lane & 3;
    const int nhalf = blockIdx.x & 1;
    const int t0 = blockIdx.x >> 1, tstep = gridDim.x >> 1;
    const int m0w = (w & 3) * 32, n0l = (w >> 2) * 64;
    const int colbase = nhalf * 128;
    const int sr = tid >> 1, sq = tid & 1;

    for (int e = tid; e < 1024; e += 256) {
        int n = e >> 3, kc = e & 7;
        int off = n * 128 + ((kc ^ n) & 7) * 16;
        *(uint4*)(smem + off) = *(const uint4*)(g_w3 + (colbase + n) * 64 + kc * 8);
    }

    {   // prologue: prefetch tile t0 -> buf0
        int grow = (t0 << 7) + sr;
        int sz = (grow < N) ? 16 : 0;
        const __half* src = g_mid2 + (size_t)(grow < N ? grow : 0) * 64;
        #pragma unroll
        for (int j = 0; j < 4; j++) {
            int c = sq * 4 + j;
            uint32_t off = sr * 128 + ((c ^ sr) & 7) * 16;
            cpa16(AU + off, src + c * 8, sz);
        }
        CP_COMMIT();
    }

    int cnt = 0;
    for (int t = t0; t < tiles; t += tstep) {
        const int row0 = t << 7;
        const int b = cnt & 1;
        {   // prefetch next tile into other buffer
            int grow = ((t + tstep) << 7) + sr;
            int sz = (grow < N) ? 16 : 0;
            const __half* src = g_mid2 + (size_t)(grow < N ? grow : 0) * 64;
            uint32_t Ab = AU + (b ^ 1) * 16384;
            #pragma unroll
            for (int j = 0; j < 4; j++) {
                int c = sq * 4 + j;
                uint32_t off = sr * 128 + ((c ^ sr) & 7) * 16;
                cpa16(Ab + off, src + c * 8, sz);
            }
            CP_COMMIT();
        }
        CP_WAIT1();
        __syncthreads();

        const uint32_t AbU = AU + b * 16384;
        float C[2][8][4] = {};
        #pragma unroll
        for (int s = 0; s < 4; s++) {
            AF a0 = load_af(AbU, lane, m0w, s * 2);
            AF a1 = load_af(AbU, lane, m0w + 16, s * 2);
            #pragma unroll
            for (int nb = 0; nb < 4; nb++) {
                BF bb = load_bf(smU, 128, lane, n0l + nb * 16, s * 2);
                mma_f16(C[0][2 * nb],     a0.h, bb.h[0], bb.h[1]);
                mma_f16(C[0][2 * nb + 1], a0.h, bb.h[2], bb.h[3]);
                mma_f16(C[1][2 * nb],     a1.h, bb.h[0], bb.h[1]);
                mma_f16(C[1][2 * nb + 1], a1.h, bb.h[2], bb.h[3]);
            }
        }
        #pragma unroll
        for (int mf = 0; mf < 2; mf++)
        #pragma unroll
        for (int nf = 0; nf < 8; nf++) {
            int row = row0 + m0w + mf * 16 + g;
            int col = colbase + n0l + nf * 8 + 2 * tg;
            float s0 = __ldg(scale + col), s1 = __ldg(scale + col + 1);
            float bb0 = __ldg(bias + col), bb1 = __ldg(bias + col + 1);
            if (row < N) {
                float2 f = *(const float2*)(feat + (size_t)row * 256 + col);
                stcs2(out + (size_t)row * 256 + col,
                      fmaxf(fmaf(C[mf][nf][0], s0, bb0) + f.x, 0.f),
                      fmaxf(fmaf(C[mf][nf][1], s1, bb1) + f.y, 0.f));
            }
            if (row + 8 < N) {
                float2 f = *(const float2*)(feat + (size_t)(row + 8) * 256 + col);
                stcs2(out + (size_t)(row + 8) * 256 + col,
                      fmaxf(fmaf(C[mf][nf][2], s0, bb0) + f.x, 0.f),
                      fmaxf(fmaf(C[mf][nf][3], s1, bb1) + f.y, 0.f));
            }
        }
        __syncthreads();
        cnt++;
    }
}

// ---------------------------------------------------------------------------
extern "C" void kernel_launch(void* const* d_in, const int* in_sizes, int n_in,
                              void* d_out, int out_size)
{
    const float* feat = (const float*)d_in[0];
    const int*   nbr  = (const int*)  d_in[1];
    const float* w1   = (const float*)d_in[2];
    const float* s1   = (const float*)d_in[3];
    const float* b1   = (const float*)d_in[4];
    const float* w2   = (const float*)d_in[5];
    const float* s2   = (const float*)d_in[6];
    const float* b2   = (const float*)d_in[7];
    const float* w3   = (const float*)d_in[8];
    const float* s3   = (const float*)d_in[9];
    const float* b3   = (const float*)d_in[10];
    float* out = (float*)d_out;

    int N = in_sizes[0] / 256;
    if (N > MAX_N) N = MAX_N;
    int tiles64  = (N + 63) >> 6;
    int tiles128 = (N + 127) >> 7;

    const int sm1 = 49152;    // 48KB  -> 3 CTAs/SM
    const int sm2 = 114688;   // 112KB -> 2 CTAs/SM
    const int sm3 = 49152;    // 48KB  -> 2 CTAs/SM

    cudaFuncSetAttribute(conv1_k, cudaFuncAttributeMaxDynamicSharedMemorySize, sm1);
    cudaFuncSetAttribute(conv2_k, cudaFuncAttributeMaxDynamicSharedMemorySize, sm2);
    cudaFuncSetAttribute(conv3_k, cudaFuncAttributeMaxDynamicSharedMemorySize, sm3);

    prep_weights<<<64, 256>>>(w1, w2, w3);
    conv1_k<<<444, 256, sm1>>>(feat, s1, b1, N, tiles64);
    conv2_k<<<296, 256, sm2>>>(nbr, s2, b2, N, tiles64);
    conv3_k<<<296, 256, sm3>>>(feat, s3, b3, out, N, tiles128);
}